// round 3
// baseline (speedup 1.0000x reference)
#include <cuda_runtime.h>
#include <math.h>

// Problem constants
#define B_ 2048
#define M_ 8192
#define D_ 512
#define H_ 8
#define HD_ 64
#define DECAY 0.9f

// ---------------- scratch (static __device__ arrays; ~104 MB total) -----------
__device__ float g_Qp[B_ * D_];           // 4 MB
__device__ float g_Kp[M_ * D_];           // 16 MB
__device__ float g_Vp[M_ * D_];           // 16 MB
__device__ float g_S1[(long)B_ * M_];     // 64 MB  (one head's scores -> w)
__device__ float g_ctx[B_ * D_];          // 4 MB
__device__ float g_tw[M_];
__device__ float g_qn[B_];
__device__ float g_kn[M_];
__device__ unsigned int g_nov[B_];        // novelty as float bits (nonneg -> uint order)

// ---------------- small helpers ----------------
__device__ __forceinline__ float blockReduceMaxF(float v, float* red) {
    int t = threadIdx.x;
    red[t] = v; __syncthreads();
    for (int s = blockDim.x >> 1; s > 0; s >>= 1) {
        if (t < s) red[t] = fmaxf(red[t], red[t + s]);
        __syncthreads();
    }
    float r = red[0]; __syncthreads();
    return r;
}
__device__ __forceinline__ float blockReduceSumF(float v, float* red) {
    int t = threadIdx.x;
    red[t] = v; __syncthreads();
    for (int s = blockDim.x >> 1; s > 0; s >>= 1) {
        if (t < s) red[t] += red[t + s];
        __syncthreads();
    }
    float r = red[0]; __syncthreads();
    return r;
}

// ---------------- zero fill ----------------------------------------------------
__global__ void fill_zero(float* __restrict__ p, long n) {
    long i = (long)blockIdx.x * blockDim.x + threadIdx.x;
    long stride = (long)gridDim.x * blockDim.x;
    for (; i < n; i += stride) p[i] = 0.f;
}
__global__ void zero_ctx() {
    long i = (long)blockIdx.x * blockDim.x + threadIdx.x;
    if (i < (long)B_ * D_) g_ctx[i] = 0.f;
}

// ---------------- timestamps max + temporal weights ---------------------------
__global__ void tw_kernel(const float* __restrict__ ts) {
    __shared__ float red[1024];
    int t = threadIdx.x;
    float m = -1e30f;
    #pragma unroll
    for (int i = 0; i < M_ / 1024; i++) m = fmaxf(m, ts[t + 1024 * i]);
    float ct = blockReduceMaxF(m, red) + 1.0f;
    #pragma unroll
    for (int i = 0; i < M_ / 1024; i++) {
        int j = t + 1024 * i;
        g_tw[j] = __expf(-DECAY * (ct - ts[j]));
    }
}

// ---------------- row sum-of-squares into g_qn / g_kn -------------------------
__device__ __forceinline__ void row_sumsq_body(const float* __restrict__ X,
                                               float* __restrict__ out) {
    __shared__ float red[128];
    const float* p = X + (long)blockIdx.x * D_;
    float s = 0.f;
    #pragma unroll
    for (int i = 0; i < D_ / 128; i++) {
        float v = p[threadIdx.x + 128 * i];
        s += v * v;
    }
    s = blockReduceSumF(s, red);
    if (threadIdx.x == 0) out[blockIdx.x] = s;
}
__global__ void row_sumsq_q(const float* __restrict__ X) { row_sumsq_body(X, g_qn); }
__global__ void row_sumsq_k(const float* __restrict__ X) { row_sumsq_body(X, g_kn); }

__global__ void init_nov() {
    int i = blockIdx.x * blockDim.x + threadIdx.x;
    if (i < B_) g_nov[i] = 0x7f800000u; // +inf
}

// ---------------- generic NT SGEMM body: C = scale*(A@B^T) (+bias) ------------
// A: [Mr, K] row-major (lda), Bm: [Nc, K] row-major (ldb), C: [Mr, Nc] (ldc)
// BM=BN=128, BK=16, 256 threads, 8x8 microtile.
#define GBM 128
#define GBN 128
#define GBK 16
__device__ __forceinline__ void sgemm_nt_body(
    const float* __restrict__ A, int lda,
    const float* __restrict__ Bm, int ldb,
    float* __restrict__ C, long ldc, int K,
    const float* __restrict__ bias, float scale)
{
    __shared__ float As[GBK][GBM + 1];
    __shared__ float Bs[GBK][GBN + 1];
    int row0 = blockIdx.y * GBM;
    int col0 = blockIdx.x * GBN;
    int tid = threadIdx.x;
    int tx = tid & 15, ty = tid >> 4;

    float acc[8][8];
    #pragma unroll
    for (int i = 0; i < 8; i++)
        #pragma unroll
        for (int j = 0; j < 8; j++) acc[i][j] = 0.f;

    for (int k0 = 0; k0 < K; k0 += GBK) {
        #pragma unroll
        for (int i = 0; i < 2; i++) {
            int e = tid + i * 256;        // [0,512)
            int r = e >> 2, c = (e & 3) * 4;
            float4 va = *(const float4*)(A + (long)(row0 + r) * lda + k0 + c);
            As[c + 0][r] = va.x; As[c + 1][r] = va.y;
            As[c + 2][r] = va.z; As[c + 3][r] = va.w;
            float4 vb = *(const float4*)(Bm + (long)(col0 + r) * ldb + k0 + c);
            Bs[c + 0][r] = vb.x; Bs[c + 1][r] = vb.y;
            Bs[c + 2][r] = vb.z; Bs[c + 3][r] = vb.w;
        }
        __syncthreads();
        #pragma unroll
        for (int k = 0; k < GBK; k++) {
            float a[8], b[8];
            #pragma unroll
            for (int i = 0; i < 8; i++) a[i] = As[k][ty + 16 * i];
            #pragma unroll
            for (int j = 0; j < 8; j++) b[j] = Bs[k][tx + 16 * j];
            #pragma unroll
            for (int i = 0; i < 8; i++)
                #pragma unroll
                for (int j = 0; j < 8; j++) acc[i][j] += a[i] * b[j];
        }
        __syncthreads();
    }
    #pragma unroll
    for (int i = 0; i < 8; i++) {
        int r = row0 + ty + 16 * i;
        #pragma unroll
        for (int j = 0; j < 8; j++) {
            int c = col0 + tx + 16 * j;
            float v = acc[i][j] * scale;
            if (bias) v += bias[c];
            C[(long)r * ldc + c] = v;
        }
    }
}

// Wrappers
__global__ __launch_bounds__(256) void proj_q_kernel(
    const float* __restrict__ X, const float* __restrict__ W,
    const float* __restrict__ bias) {
    sgemm_nt_body(X, D_, W, D_, g_Qp, D_, D_, bias, 1.f);
}
__global__ __launch_bounds__(256) void proj_k_kernel(
    const float* __restrict__ X, const float* __restrict__ W,
    const float* __restrict__ bias) {
    sgemm_nt_body(X, D_, W, D_, g_Kp, D_, D_, bias, 1.f);
}
__global__ __launch_bounds__(256) void proj_v_kernel(
    const float* __restrict__ X, const float* __restrict__ W,
    const float* __restrict__ bias) {
    sgemm_nt_body(X, D_, W, D_, g_Vp, D_, D_, bias, 1.f);
}
// scores for head h: S1 = 0.125 * Qp[:,h*64:+64] @ Kp[:,h*64:+64]^T  (K=64)
__global__ __launch_bounds__(256) void scores_kernel(int h) {
    sgemm_nt_body(g_Qp + h * HD_, D_, g_Kp + h * HD_, D_,
                  g_S1, (long)M_, HD_, nullptr, 0.125f);
}
// values = ctx @ Wo^T + bo  (writes straight to output)
__global__ __launch_bounds__(256) void out_proj_kernel(
    const float* __restrict__ W, const float* __restrict__ bias,
    float* __restrict__ out_values) {
    sgemm_nt_body(g_ctx, D_, W, D_, out_values, D_, D_, bias, 1.f);
}

// ---------------- dist GEMM with min epilogue (novelty) -----------------------
__global__ __launch_bounds__(256) void dist_min_kernel(
    const float* __restrict__ qf, const float* __restrict__ ck)
{
    __shared__ float As[GBK][GBM + 1];
    __shared__ float Bs[GBK][GBN + 1];
    int row0 = blockIdx.y * GBM;
    int col0 = blockIdx.x * GBN;
    int tid = threadIdx.x;
    int tx = tid & 15, ty = tid >> 4;

    float acc[8][8];
    #pragma unroll
    for (int i = 0; i < 8; i++)
        #pragma unroll
        for (int j = 0; j < 8; j++) acc[i][j] = 0.f;

    for (int k0 = 0; k0 < D_; k0 += GBK) {
        #pragma unroll
        for (int i = 0; i < 2; i++) {
            int e = tid + i * 256;
            int r = e >> 2, c = (e & 3) * 4;
            float4 va = *(const float4*)(qf + (long)(row0 + r) * D_ + k0 + c);
            As[c + 0][r] = va.x; As[c + 1][r] = va.y;
            As[c + 2][r] = va.z; As[c + 3][r] = va.w;
            float4 vb = *(const float4*)(ck + (long)(col0 + r) * D_ + k0 + c);
            Bs[c + 0][r] = vb.x; Bs[c + 1][r] = vb.y;
            Bs[c + 2][r] = vb.z; Bs[c + 3][r] = vb.w;
        }
        __syncthreads();
        #pragma unroll
        for (int k = 0; k < GBK; k++) {
            float a[8], b[8];
            #pragma unroll
            for (int i = 0; i < 8; i++) a[i] = As[k][ty + 16 * i];
            #pragma unroll
            for (int j = 0; j < 8; j++) b[j] = Bs[k][tx + 16 * j];
            #pragma unroll
            for (int i = 0; i < 8; i++)
                #pragma unroll
                for (int j = 0; j < 8; j++) acc[i][j] += a[i] * b[j];
        }
        __syncthreads();
    }
    #pragma unroll
    for (int i = 0; i < 8; i++) {
        int r = row0 + ty + 16 * i;
        float qnr = g_qn[r];
        float mn = 1e30f;
        #pragma unroll
        for (int j = 0; j < 8; j++) {
            int c = col0 + tx + 16 * j;
            float d2 = qnr + g_kn[c] - 2.f * acc[i][j];
            float v = sqrtf(fmaxf(d2, 0.f)) * g_tw[c];
            mn = fminf(mn, v);
        }
        // reduce across the 16 tx lanes (xor<16 stays within tx bits of the lane id)
        #pragma unroll
        for (int m = 8; m > 0; m >>= 1)
            mn = fminf(mn, __shfl_xor_sync(0xffffffffu, mn, m, 32));
        if (tx == 0) atomicMin(&g_nov[r], __float_as_uint(mn));
    }
}

// ------- per-row softmax of S1 (one head) + accumulate mean into attn ---------
// Block b owns row b. Writes w back to g_S1 and adds w/H into attn_accum[b,:].
__global__ __launch_bounds__(256) void softmax_attn_kernel(float* __restrict__ attn_accum) {
    __shared__ float red[256];
    long base = (long)blockIdx.x * M_;
    int t = threadIdx.x;
    float x[M_ / 256];
    float mx = -1e30f;
    #pragma unroll
    for (int i = 0; i < M_ / 256; i++) {
        x[i] = g_S1[base + t + 256 * i];
        mx = fmaxf(mx, x[i]);
    }
    mx = blockReduceMaxF(mx, red);
    float s = 0.f;
    #pragma unroll
    for (int i = 0; i < M_ / 256; i++) {
        x[i] = __expf(x[i] - mx);
        s += x[i];
    }
    s = blockReduceSumF(s, red);
    float inv = 1.f / s;
    #pragma unroll
    for (int i = 0; i < M_ / 256; i++) {
        long idx = base + t + 256 * i;
        float w = x[i] * inv;
        g_S1[idx] = w;
        attn_accum[idx] += w * (1.0f / H_);
    }
}

// ------- ctx split-K: g_ctx[:, h*64:+64] += S1 @ Vp[:, h*64:+64] --------------
// Grid: (KSPLIT, B/64). Each block handles a 64x64 output tile over M/KSPLIT ks.
#define CBM 64
#define CBN 64
#define CBK 32
#define KSPLIT 16
__global__ __launch_bounds__(256) void ctx_gemm_kernel(int h) {
    __shared__ float As[CBK][CBM + 1];
    __shared__ float Bs[CBK][CBN + 1];
    int row0 = blockIdx.y * CBM;
    int kslice = blockIdx.x;                 // [0, KSPLIT)
    int kbeg = kslice * (M_ / KSPLIT);
    int kend = kbeg + (M_ / KSPLIT);
    const float* A = g_S1;                   // [B, M] lda = M_
    const float* Bp = g_Vp + h * HD_;        // [M, 64] ldb = D_
    int tid = threadIdx.x;
    int tx = tid & 15, ty = tid >> 4;

    float acc[4][4];
    #pragma unroll
    for (int i = 0; i < 4; i++)
        #pragma unroll
        for (int j = 0; j < 4; j++) acc[i][j] = 0.f;

    for (int k0 = kbeg; k0 < kend; k0 += CBK) {
        #pragma unroll
        for (int i = 0; i < 2; i++) {
            int e = tid + i * 256;            // [0,512)
            int r = e >> 3, c = (e & 7) * 4;  // A: 64 rows x 32 k
            float4 va = *(const float4*)(A + (long)(row0 + r) * M_ + k0 + c);
            As[c + 0][r] = va.x; As[c + 1][r] = va.y;
            As[c + 2][r] = va.z; As[c + 3][r] = va.w;
            int kr = e >> 4, cc = (e & 15) * 4; // B: 32 k-rows x 64 j
            float4 vb = *(const float4*)(Bp + (long)(k0 + kr) * D_ + cc);
            Bs[kr][cc + 0] = vb.x; Bs[kr][cc + 1] = vb.y;
            Bs[kr][cc + 2] = vb.z; Bs[kr][cc + 3] = vb.w;
        }
        __syncthreads();
        #pragma unroll
        for (int k = 0; k < CBK; k++) {
            float a[4], b[4];
            #pragma unroll
            for (int i = 0; i < 4; i++) a[i] = As[k][ty + 16 * i];
            #pragma unroll
            for (int j = 0; j < 4; j++) b[j] = Bs[k][tx + 16 * j];
            #pragma unroll
            for (int i = 0; i < 4; i++)
                #pragma unroll
                for (int j = 0; j < 4; j++) acc[i][j] += a[i] * b[j];
        }
        __syncthreads();
    }
    #pragma unroll
    for (int i = 0; i < 4; i++) {
        int r = row0 + ty + 16 * i;
        #pragma unroll
        for (int j = 0; j < 4; j++) {
            int c = h * HD_ + tx + 16 * j;
            atomicAdd(&g_ctx[(long)r * D_ + c], acc[i][j]);
        }
    }
}

// ---------------- adjusted softmax + weighted dots + surprise -----------------
// Reads head-mean attn from out_adj, overwrites out_adj in place with adjusted.
__global__ __launch_bounds__(256) void adjusted_kernel(
    const float* __restrict__ succ, const float* __restrict__ surp,
    const float* __restrict__ grad,
    float* __restrict__ out_adj, float* __restrict__ out_ws,
    float* __restrict__ out_wp, float* __restrict__ out_surprise)
{
    __shared__ float red[256];
    int b = blockIdx.x;
    long base = (long)b * M_;
    int t = threadIdx.x;
    float x[M_ / 256];
    float mx = -1e30f;
    #pragma unroll
    for (int i = 0; i < M_ / 256; i++) {
        int m = t + 256 * i;
        x[i] = out_adj[base + m] * g_tw[m];
        mx = fmaxf(mx, x[i]);
    }
    mx = blockReduceMaxF(mx, red);
    float s = 0.f;
    #pragma unroll
    for (int i = 0; i < M_ / 256; i++) {
        x[i] = __expf(x[i] - mx);
        s += x[i];
    }
    s = blockReduceSumF(s, red);
    float inv = 1.f / s;
    float ds = 0.f, dp = 0.f;
    #pragma unroll
    for (int i = 0; i < M_ / 256; i++) {
        int m = t + 256 * i;
        float a = x[i] * inv;
        out_adj[base + m] = a;
        ds += a * succ[m];
        dp += a * surp[m];
    }
    ds = blockReduceSumF(ds, red);
    dp = blockReduceSumF(dp, red);
    if (t == 0) {
        out_ws[b] = ds;
        out_wp[b] = dp;
        out_surprise[b] = grad[b] * __uint_as_float(g_nov[b]);
    }
}

// ---------------- host launcher (kernel launches ONLY) ------------------------
extern "C" void kernel_launch(void* const* d_in, const int* in_sizes, int n_in,
                              void* d_out, int out_size) {
    const float* qf   = (const float*)d_in[0];
    const float* grad = (const float*)d_in[1];
    const float* ck   = (const float*)d_in[2];
    const float* cv   = (const float*)d_in[3];
    const float* ts   = (const float*)d_in[4];
    const float* succ = (const float*)d_in[5];
    const float* surp = (const float*)d_in[6];
    const float* Wq   = (const float*)d_in[7];
    const float* Wk   = (const float*)d_in[8];
    const float* Wv   = (const float*)d_in[9];
    const float* Wo   = (const float*)d_in[10];
    const float* bq   = (const float*)d_in[11];
    const float* bk   = (const float*)d_in[12];
    const float* bv   = (const float*)d_in[13];
    const float* bo   = (const float*)d_in[14];

    float* out_values   = (float*)d_out;                 // [B, D]
    float* out_surprise = out_values + (long)B_ * D_;    // [B]
    float* out_adjusted = out_surprise + B_;             // [B, M]
    float* out_wsucc    = out_adjusted + (long)B_ * M_;  // [B]
    float* out_wsurp    = out_wsucc + B_;                // [B]

    // 1. temporal weights
    tw_kernel<<<1, 1024>>>(ts);
    // 2. norms + novelty init + accumulator zeroing
    row_sumsq_q<<<B_, 128>>>(qf);
    row_sumsq_k<<<M_, 128>>>(ck);
    init_nov<<<(B_ + 255) / 256, 256>>>();
    fill_zero<<<2048, 256>>>(out_adjusted, (long)B_ * M_);
    zero_ctx<<<(B_ * D_ + 255) / 256, 256>>>();
    // 3. distance + min-novelty
    dist_min_kernel<<<dim3(M_ / GBN, B_ / GBM), 256>>>(qf, ck);
    // 4. projections
    proj_q_kernel<<<dim3(D_ / GBN, B_ / GBM), 256>>>(qf, Wq, bq);
    proj_k_kernel<<<dim3(D_ / GBN, M_ / GBM), 256>>>(ck, Wk, bk);
    proj_v_kernel<<<dim3(D_ / GBN, M_ / GBM), 256>>>(cv, Wv, bv);
    // 5. per-head attention (sequential heads through one 64MB scratch)
    for (int h = 0; h < H_; h++) {
        scores_kernel<<<dim3(M_ / GBN, B_ / GBM), 256>>>(h);
        softmax_attn_kernel<<<B_, 256>>>(out_adjusted);
        ctx_gemm_kernel<<<dim3(KSPLIT, B_ / CBM), 256>>>(h);
    }
    // 6. values = ctx @ Wo^T + bo
    out_proj_kernel<<<dim3(D_ / GBN, B_ / GBM), 256>>>(Wo, bo, out_values);
    // 7. adjusted softmax + weighted sums + surprise
    adjusted_kernel<<<B_, 256>>>(succ, surp, grad,
                                 out_adjusted, out_wsucc, out_wsurp, out_surprise);
}

// round 4
// speedup vs baseline: 1.8385x; 1.8385x over previous
#include <cuda_runtime.h>
#include <math.h>

// Problem constants
#define B_ 2048
#define M_ 8192
#define D_ 512
#define H_ 8
#define HD_ 64
#define DECAY 0.9f

// ---------------- scratch (static __device__ arrays; ~104 MB total) -----------
__device__ float g_Qp[B_ * D_];           // 4 MB
__device__ float g_Kp[M_ * D_];           // 16 MB
__device__ float g_Vp[M_ * D_];           // 16 MB
__device__ float g_S1[(long)B_ * M_];     // 64 MB  (one head's scores -> w)
__device__ float g_ctx[B_ * D_];          // 4 MB
__device__ float g_tw[M_];
__device__ float g_qn[B_];
__device__ float g_kn[M_];
__device__ unsigned int g_nov[B_];        // novelty as float bits (nonneg -> uint order)

// ---------------- tf32 mma helpers ----------------
__device__ __forceinline__ unsigned f2tf(float x) {
    unsigned r;
    asm("cvt.rna.tf32.f32 %0, %1;" : "=r"(r) : "f"(x));
    return r;
}
__device__ __forceinline__ void mma_tf32(float* c, const unsigned* a, const unsigned* b) {
    asm volatile(
        "mma.sync.aligned.m16n8k8.row.col.f32.tf32.tf32.f32 "
        "{%0,%1,%2,%3}, {%4,%5,%6,%7}, {%8,%9}, {%0,%1,%2,%3};\n"
        : "+f"(c[0]), "+f"(c[1]), "+f"(c[2]), "+f"(c[3])
        : "r"(a[0]), "r"(a[1]), "r"(a[2]), "r"(a[3]), "r"(b[0]), "r"(b[1]));
}

// ---------------- small helpers ----------------
__device__ __forceinline__ float blockReduceMaxF(float v, float* red) {
    int t = threadIdx.x;
    red[t] = v; __syncthreads();
    for (int s = blockDim.x >> 1; s > 0; s >>= 1) {
        if (t < s) red[t] = fmaxf(red[t], red[t + s]);
        __syncthreads();
    }
    float r = red[0]; __syncthreads();
    return r;
}
__device__ __forceinline__ float blockReduceSumF(float v, float* red) {
    int t = threadIdx.x;
    red[t] = v; __syncthreads();
    for (int s = blockDim.x >> 1; s > 0; s >>= 1) {
        if (t < s) red[t] += red[t + s];
        __syncthreads();
    }
    float r = red[0]; __syncthreads();
    return r;
}

// ---------------- zero fill ----------------------------------------------------
__global__ void fill_zero(float* __restrict__ p, long n) {
    long i = (long)blockIdx.x * blockDim.x + threadIdx.x;
    long stride = (long)gridDim.x * blockDim.x;
    for (; i < n; i += stride) p[i] = 0.f;
}
__global__ void zero_ctx() {
    long i = (long)blockIdx.x * blockDim.x + threadIdx.x;
    if (i < (long)B_ * D_) g_ctx[i] = 0.f;
}

// ---------------- timestamps max + temporal weights ---------------------------
__global__ void tw_kernel(const float* __restrict__ ts) {
    __shared__ float red[1024];
    int t = threadIdx.x;
    float m = -1e30f;
    #pragma unroll
    for (int i = 0; i < M_ / 1024; i++) m = fmaxf(m, ts[t + 1024 * i]);
    float ct = blockReduceMaxF(m, red) + 1.0f;
    #pragma unroll
    for (int i = 0; i < M_ / 1024; i++) {
        int j = t + 1024 * i;
        g_tw[j] = __expf(-DECAY * (ct - ts[j]));
    }
}

// ---------------- row sum-of-squares into g_qn / g_kn -------------------------
__device__ __forceinline__ void row_sumsq_body(const float* __restrict__ X,
                                               float* __restrict__ out) {
    __shared__ float red[128];
    const float* p = X + (long)blockIdx.x * D_;
    float s = 0.f;
    #pragma unroll
    for (int i = 0; i < D_ / 128; i++) {
        float v = p[threadIdx.x + 128 * i];
        s += v * v;
    }
    s = blockReduceSumF(s, red);
    if (threadIdx.x == 0) out[blockIdx.x] = s;
}
__global__ void row_sumsq_q(const float* __restrict__ X) { row_sumsq_body(X, g_qn); }
__global__ void row_sumsq_k(const float* __restrict__ X) { row_sumsq_body(X, g_kn); }

__global__ void init_nov() {
    int i = blockIdx.x * blockDim.x + threadIdx.x;
    if (i < B_) g_nov[i] = 0x7f800000u; // +inf
}

// ============ generic NT tf32 GEMM body: C = scale*(A@B^T) (+bias) ============
// A: [Mr, K] row-major, Bm: [Nc, K] row-major. Block 128x128, BK=32.
// 8 warps: 2(M) x 4(N), warp tile 64x32 (mf=4 m16-frags, nf=4 n8-frags).
#define TBM 128
#define TBN 128
#define TBK 32
#define APITCH 36
__device__ __forceinline__ void tgemm_nt_body(
    const float* __restrict__ A, int lda,
    const float* __restrict__ Bm, int ldb,
    float* __restrict__ C, long ldc, int K,
    const float* __restrict__ bias, float scale)
{
    __shared__ unsigned As[TBM][APITCH];
    __shared__ unsigned Bs[TBN][APITCH];
    int row0 = blockIdx.y * TBM;
    int col0 = blockIdx.x * TBN;
    int tid = threadIdx.x;
    int warp = tid >> 5, lane = tid & 31;
    int g = lane >> 2, q = lane & 3;
    int warpM = warp & 1, warpN = warp >> 1;
    int rA = warpM * 64, cB = warpN * 32;

    float acc[4][4][4];
    #pragma unroll
    for (int i = 0; i < 4; i++)
        #pragma unroll
        for (int j = 0; j < 4; j++)
            #pragma unroll
            for (int r = 0; r < 4; r++) acc[i][j][r] = 0.f;

    for (int k0 = 0; k0 < K; k0 += TBK) {
        #pragma unroll
        for (int i = 0; i < 4; i++) {
            int idx = tid + i * 256;      // [0,1024)
            int r = idx >> 3, kq = (idx & 7) << 2;
            float4 va = *(const float4*)(A + (long)(row0 + r) * lda + k0 + kq);
            As[r][kq + 0] = f2tf(va.x); As[r][kq + 1] = f2tf(va.y);
            As[r][kq + 2] = f2tf(va.z); As[r][kq + 3] = f2tf(va.w);
            float4 vb = *(const float4*)(Bm + (long)(col0 + r) * ldb + k0 + kq);
            Bs[r][kq + 0] = f2tf(vb.x); Bs[r][kq + 1] = f2tf(vb.y);
            Bs[r][kq + 2] = f2tf(vb.z); Bs[r][kq + 3] = f2tf(vb.w);
        }
        __syncthreads();
        #pragma unroll
        for (int s = 0; s < TBK / 8; s++) {
            int ks = s * 8;
            unsigned af[4][4], bf[4][2];
            #pragma unroll
            for (int mf = 0; mf < 4; mf++) {
                int rb = rA + mf * 16;
                af[mf][0] = As[rb + g][ks + q];
                af[mf][1] = As[rb + g + 8][ks + q];
                af[mf][2] = As[rb + g][ks + q + 4];
                af[mf][3] = As[rb + g + 8][ks + q + 4];
            }
            #pragma unroll
            for (int nf = 0; nf < 4; nf++) {
                int nb = cB + nf * 8;
                bf[nf][0] = Bs[nb + g][ks + q];
                bf[nf][1] = Bs[nb + g][ks + q + 4];
            }
            #pragma unroll
            for (int mf = 0; mf < 4; mf++)
                #pragma unroll
                for (int nf = 0; nf < 4; nf++)
                    mma_tf32(acc[mf][nf], af[mf], bf[nf]);
        }
        __syncthreads();
    }
    // epilogue: c0,c1 at (row g, cols 2q,2q+1); c2,c3 at row g+8
    #pragma unroll
    for (int mf = 0; mf < 4; mf++) {
        #pragma unroll
        for (int half = 0; half < 2; half++) {
            int r = row0 + rA + mf * 16 + g + half * 8;
            #pragma unroll
            for (int nf = 0; nf < 4; nf++) {
                int c = col0 + cB + nf * 8 + q * 2;
                float v0 = acc[mf][nf][half * 2 + 0] * scale;
                float v1 = acc[mf][nf][half * 2 + 1] * scale;
                if (bias) { v0 += bias[c]; v1 += bias[c + 1]; }
                *(float2*)(C + (long)r * ldc + c) = make_float2(v0, v1);
            }
        }
    }
}

// Wrappers
__global__ __launch_bounds__(256, 2) void proj_q_kernel(
    const float* __restrict__ X, const float* __restrict__ W,
    const float* __restrict__ bias) {
    tgemm_nt_body(X, D_, W, D_, g_Qp, D_, D_, bias, 1.f);
}
__global__ __launch_bounds__(256, 2) void proj_k_kernel(
    const float* __restrict__ X, const float* __restrict__ W,
    const float* __restrict__ bias) {
    tgemm_nt_body(X, D_, W, D_, g_Kp, D_, D_, bias, 1.f);
}
__global__ __launch_bounds__(256, 2) void proj_v_kernel(
    const float* __restrict__ X, const float* __restrict__ W,
    const float* __restrict__ bias) {
    tgemm_nt_body(X, D_, W, D_, g_Vp, D_, D_, bias, 1.f);
}
__global__ __launch_bounds__(256, 2) void scores_kernel(int h) {
    tgemm_nt_body(g_Qp + h * HD_, D_, g_Kp + h * HD_, D_,
                  g_S1, (long)M_, HD_, nullptr, 0.125f);
}
__global__ __launch_bounds__(256, 2) void out_proj_kernel(
    const float* __restrict__ W, const float* __restrict__ bias,
    float* __restrict__ out_values) {
    tgemm_nt_body(g_ctx, D_, W, D_, out_values, D_, D_, bias, 1.f);
}

// ============ dist GEMM (tf32) with min epilogue (novelty) ====================
__global__ __launch_bounds__(256, 2) void dist_min_kernel(
    const float* __restrict__ qf, const float* __restrict__ ck)
{
    __shared__ unsigned As[TBM][APITCH];
    __shared__ unsigned Bs[TBN][APITCH];
    __shared__ unsigned smin[TBM];
    int row0 = blockIdx.y * TBM;
    int col0 = blockIdx.x * TBN;
    int tid = threadIdx.x;
    int warp = tid >> 5, lane = tid & 31;
    int g = lane >> 2, q = lane & 3;
    int warpM = warp & 1, warpN = warp >> 1;
    int rA = warpM * 64, cB = warpN * 32;

    if (tid < TBM) smin[tid] = 0x7f800000u;

    float acc[4][4][4];
    #pragma unroll
    for (int i = 0; i < 4; i++)
        #pragma unroll
        for (int j = 0; j < 4; j++)
            #pragma unroll
            for (int r = 0; r < 4; r++) acc[i][j][r] = 0.f;

    for (int k0 = 0; k0 < D_; k0 += TBK) {
        #pragma unroll
        for (int i = 0; i < 4; i++) {
            int idx = tid + i * 256;
            int r = idx >> 3, kq = (idx & 7) << 2;
            float4 va = *(const float4*)(qf + (long)(row0 + r) * D_ + k0 + kq);
            As[r][kq + 0] = f2tf(va.x); As[r][kq + 1] = f2tf(va.y);
            As[r][kq + 2] = f2tf(va.z); As[r][kq + 3] = f2tf(va.w);
            float4 vb = *(const float4*)(ck + (long)(col0 + r) * D_ + k0 + kq);
            Bs[r][kq + 0] = f2tf(vb.x); Bs[r][kq + 1] = f2tf(vb.y);
            Bs[r][kq + 2] = f2tf(vb.z); Bs[r][kq + 3] = f2tf(vb.w);
        }
        __syncthreads();
        #pragma unroll
        for (int s = 0; s < TBK / 8; s++) {
            int ks = s * 8;
            unsigned af[4][4], bf[4][2];
            #pragma unroll
            for (int mf = 0; mf < 4; mf++) {
                int rb = rA + mf * 16;
                af[mf][0] = As[rb + g][ks + q];
                af[mf][1] = As[rb + g + 8][ks + q];
                af[mf][2] = As[rb + g][ks + q + 4];
                af[mf][3] = As[rb + g + 8][ks + q + 4];
            }
            #pragma unroll
            for (int nf = 0; nf < 4; nf++) {
                int nb = cB + nf * 8;
                bf[nf][0] = Bs[nb + g][ks + q];
                bf[nf][1] = Bs[nb + g][ks + q + 4];
            }
            #pragma unroll
            for (int mf = 0; mf < 4; mf++)
                #pragma unroll
                for (int nf = 0; nf < 4; nf++)
                    mma_tf32(acc[mf][nf], af[mf], bf[nf]);
        }
        __syncthreads();
    }
    // epilogue: d2 = qn + kn - 2*dot -> dist*tw -> min per row
    #pragma unroll
    for (int mf = 0; mf < 4; mf++) {
        #pragma unroll
        for (int half = 0; half < 2; half++) {
            int r = row0 + rA + mf * 16 + g + half * 8;
            float qnr = g_qn[r];
            float mn = 1e30f;
            #pragma unroll
            for (int nf = 0; nf < 4; nf++) {
                #pragma unroll
                for (int j = 0; j < 2; j++) {
                    int c = col0 + cB + nf * 8 + q * 2 + j;
                    float d2 = qnr + g_kn[c] - 2.f * acc[mf][nf][half * 2 + j];
                    float v = sqrtf(fmaxf(d2, 0.f)) * g_tw[c];
                    mn = fminf(mn, v);
                }
            }
            // min over the 4 lanes of the quad (bits 0,1)
            mn = fminf(mn, __shfl_xor_sync(0xffffffffu, mn, 1, 32));
            mn = fminf(mn, __shfl_xor_sync(0xffffffffu, mn, 2, 32));
            if (q == 0) atomicMin(&smin[rA + mf * 16 + g + half * 8], __float_as_uint(mn));
        }
    }
    __syncthreads();
    if (tid < TBM) atomicMin(&g_nov[row0 + tid], smin[tid]);
}

// ------- per-row softmax of S1 (one head) + accumulate mean into attn ---------
__global__ __launch_bounds__(256) void softmax_attn_kernel(float* __restrict__ attn_accum) {
    __shared__ float red[256];
    long base = (long)blockIdx.x * M_;
    int t = threadIdx.x;
    float x[M_ / 256];
    float mx = -1e30f;
    #pragma unroll
    for (int i = 0; i < M_ / 256; i++) {
        x[i] = g_S1[base + t + 256 * i];
        mx = fmaxf(mx, x[i]);
    }
    mx = blockReduceMaxF(mx, red);
    float s = 0.f;
    #pragma unroll
    for (int i = 0; i < M_ / 256; i++) {
        x[i] = __expf(x[i] - mx);
        s += x[i];
    }
    s = blockReduceSumF(s, red);
    float inv = 1.f / s;
    #pragma unroll
    for (int i = 0; i < M_ / 256; i++) {
        long idx = base + t + 256 * i;
        float w = x[i] * inv;
        g_S1[idx] = w;
        attn_accum[idx] += w * (1.0f / H_);
    }
}

// ============ ctx NN tf32 GEMM: g_ctx[:, h*64:+64] += S1 @ Vp[:, h*64:+64] ====
// A = S1 [B, M] (k-major rows), B = Vp slice [M, 64] (k-major). Split-K + atomics.
#define XBM 128
#define XBN 64
#define XBK 32
#define BPITCH 72
#define KSPLIT 8
__global__ __launch_bounds__(256, 2) void ctx_gemm_kernel(int h) {
    __shared__ unsigned As[XBM][APITCH];
    __shared__ unsigned Bs[XBK][BPITCH];
    int row0 = blockIdx.y * XBM;
    int kbeg = blockIdx.x * (M_ / KSPLIT);
    int kend = kbeg + (M_ / KSPLIT);
    int hbase = h * HD_;
    int tid = threadIdx.x;
    int warp = tid >> 5, lane = tid & 31;
    int g = lane >> 2, q = lane & 3;
    int warpM = warp & 3, warpN = warp >> 2;   // 4(M) x 2(N), warp tile 32x32
    int rA = warpM * 32, cB = warpN * 32;

    float acc[2][4][4];
    #pragma unroll
    for (int i = 0; i < 2; i++)
        #pragma unroll
        for (int j = 0; j < 4; j++)
            #pragma unroll
            for (int r = 0; r < 4; r++) acc[i][j][r] = 0.f;

    for (int k0 = kbeg; k0 < kend; k0 += XBK) {
        #pragma unroll
        for (int i = 0; i < 4; i++) {
            int idx = tid + i * 256;
            int r = idx >> 3, kq = (idx & 7) << 2;
            float4 va = *(const float4*)(g_S1 + (long)(row0 + r) * M_ + k0 + kq);
            As[r][kq + 0] = f2tf(va.x); As[r][kq + 1] = f2tf(va.y);
            As[r][kq + 2] = f2tf(va.z); As[r][kq + 3] = f2tf(va.w);
        }
        #pragma unroll
        for (int i = 0; i < 2; i++) {
            int idx = tid + i * 256;      // [0,512)
            int k = idx >> 4, n4 = (idx & 15) << 2;
            float4 vb = *(const float4*)(g_Vp + (long)(k0 + k) * D_ + hbase + n4);
            Bs[k][n4 + 0] = f2tf(vb.x); Bs[k][n4 + 1] = f2tf(vb.y);
            Bs[k][n4 + 2] = f2tf(vb.z); Bs[k][n4 + 3] = f2tf(vb.w);
        }
        __syncthreads();
        #pragma unroll
        for (int s = 0; s < XBK / 8; s++) {
            int ks = s * 8;
            unsigned af[2][4], bf[4][2];
            #pragma unroll
            for (int mf = 0; mf < 2; mf++) {
                int rb = rA + mf * 16;
                af[mf][0] = As[rb + g][ks + q];
                af[mf][1] = As[rb + g + 8][ks + q];
                af[mf][2] = As[rb + g][ks + q + 4];
                af[mf][3] = As[rb + g + 8][ks + q + 4];
            }
            #pragma unroll
            for (int nf = 0; nf < 4; nf++) {
                int nb = cB + nf * 8;
                bf[nf][0] = Bs[ks + q][nb + g];
                bf[nf][1] = Bs[ks + q + 4][nb + g];
            }
            #pragma unroll
            for (int mf = 0; mf < 2; mf++)
                #pragma unroll
                for (int nf = 0; nf < 4; nf++)
                    mma_tf32(acc[mf][nf], af[mf], bf[nf]);
        }
        __syncthreads();
    }
    #pragma unroll
    for (int mf = 0; mf < 2; mf++) {
        #pragma unroll
        for (int half = 0; half < 2; half++) {
            int r = row0 + rA + mf * 16 + g + half * 8;
            #pragma unroll
            for (int nf = 0; nf < 4; nf++) {
                int c = hbase + cB + nf * 8 + q * 2;
                atomicAdd(&g_ctx[(long)r * D_ + c],     acc[mf][nf][half * 2 + 0]);
                atomicAdd(&g_ctx[(long)r * D_ + c + 1], acc[mf][nf][half * 2 + 1]);
            }
        }
    }
}

// ---------------- adjusted softmax + weighted dots + surprise -----------------
__global__ __launch_bounds__(256) void adjusted_kernel(
    const float* __restrict__ succ, const float* __restrict__ surp,
    const float* __restrict__ grad,
    float* __restrict__ out_adj, float* __restrict__ out_ws,
    float* __restrict__ out_wp, float* __restrict__ out_surprise)
{
    __shared__ float red[256];
    int b = blockIdx.x;
    long base = (long)b * M_;
    int t = threadIdx.x;
    float x[M_ / 256];
    float mx = -1e30f;
    #pragma unroll
    for (int i = 0; i < M_ / 256; i++) {
        int m = t + 256 * i;
        x[i] = out_adj[base + m] * g_tw[m];
        mx = fmaxf(mx, x[i]);
    }
    mx = blockReduceMaxF(mx, red);
    float s = 0.f;
    #pragma unroll
    for (int i = 0; i < M_ / 256; i++) {
        x[i] = __expf(x[i] - mx);
        s += x[i];
    }
    s = blockReduceSumF(s, red);
    float inv = 1.f / s;
    float ds = 0.f, dp = 0.f;
    #pragma unroll
    for (int i = 0; i < M_ / 256; i++) {
        int m = t + 256 * i;
        float a = x[i] * inv;
        out_adj[base + m] = a;
        ds += a * succ[m];
        dp += a * surp[m];
    }
    ds = blockReduceSumF(ds, red);
    dp = blockReduceSumF(dp, red);
    if (t == 0) {
        out_ws[b] = ds;
        out_wp[b] = dp;
        out_surprise[b] = grad[b] * __uint_as_float(g_nov[b]);
    }
}

// ---------------- host launcher (kernel launches ONLY) ------------------------
extern "C" void kernel_launch(void* const* d_in, const int* in_sizes, int n_in,
                              void* d_out, int out_size) {
    const float* qf   = (const float*)d_in[0];
    const float* grad = (const float*)d_in[1];
    const float* ck   = (const float*)d_in[2];
    const float* cv   = (const float*)d_in[3];
    const float* ts   = (const float*)d_in[4];
    const float* succ = (const float*)d_in[5];
    const float* surp = (const float*)d_in[6];
    const float* Wq   = (const float*)d_in[7];
    const float* Wk   = (const float*)d_in[8];
    const float* Wv   = (const float*)d_in[9];
    const float* Wo   = (const float*)d_in[10];
    const float* bq   = (const float*)d_in[11];
    const float* bk   = (const float*)d_in[12];
    const float* bv   = (const float*)d_in[13];
    const float* bo   = (const float*)d_in[14];

    float* out_values   = (float*)d_out;                 // [B, D]
    float* out_surprise = out_values + (long)B_ * D_;    // [B]
    float* out_adjusted = out_surprise + B_;             // [B, M]
    float* out_wsucc    = out_adjusted + (long)B_ * M_;  // [B]
    float* out_wsurp    = out_wsucc + B_;                // [B]

    // 1. temporal weights
    tw_kernel<<<1, 1024>>>(ts);
    // 2. norms + novelty init + accumulator zeroing
    row_sumsq_q<<<B_, 128>>>(qf);
    row_sumsq_k<<<M_, 128>>>(ck);
    init_nov<<<(B_ + 255) / 256, 256>>>();
    fill_zero<<<2048, 256>>>(out_adjusted, (long)B_ * M_);
    zero_ctx<<<(B_ * D_ + 255) / 256, 256>>>();
    // 3. distance + min-novelty (tf32 tensor)
    dist_min_kernel<<<dim3(M_ / TBN, B_ / TBM), 256>>>(qf, ck);
    // 4. projections (tf32 tensor)
    proj_q_kernel<<<dim3(D_ / TBN, B_ / TBM), 256>>>(qf, Wq, bq);
    proj_k_kernel<<<dim3(D_ / TBN, M_ / TBM), 256>>>(ck, Wk, bk);
    proj_v_kernel<<<dim3(D_ / TBN, M_ / TBM), 256>>>(cv, Wv, bv);
    // 5. per-head attention (sequential heads through one 64MB scratch)
    for (int h = 0; h < H_; h++) {
        scores_kernel<<<dim3(M_ / TBN, B_ / TBM), 256>>>(h);
        softmax_attn_kernel<<<B_, 256>>>(out_adjusted);
        ctx_gemm_kernel<<<dim3(KSPLIT, B_ / XBM), 256>>>(h);
    }
    // 6. values = ctx @ Wo^T + bo (tf32 tensor)
    out_proj_kernel<<<dim3(D_ / TBN, B_ / TBM), 256>>>(Wo, bo, out_values);
    // 7. adjusted softmax + weighted sums + surprise
    adjusted_kernel<<<B_, 256>>>(succ, surp, grad,
                                 out_adjusted, out_wsucc, out_wsurp, out_surprise);
}